// round 16
// baseline (speedup 1.0000x reference)
#include <cuda_runtime.h>
#include <stdint.h>

#define NB      16
#define NCLS    80
#define NANCH   17064
#define NQUAD   (NANCH / 4)     // 4266
#define TOPK    1000
#define NBUCK   2048
#define CANDCAP 4096

// ---------------- scratch (static device globals, zero-initialized at load) ----------------
__device__ float              d_score[NB * NANCH];
__device__ int                d_cls  [NB * NANCH];
__device__ float4             d_box  [NB * NANCH];
__device__ int                d_hist [NB * NBUCK];
__device__ int                d_cut  [NB];
__device__ int                d_cnt  [NB];
__device__ int                d_candanch[NB * CANDCAP];
__device__ unsigned long long d_cand [NB * CANDCAP];
__device__ float              d_tscore[NB * TOPK];
__device__ int                d_tcls  [NB * TOPK];
__device__ float4             d_tbox  [NB * TOPK];
__device__ float4             d_nbox  [NB * TOPK];
__device__ float              d_narea [NB * TOPK];
__device__ unsigned           d_mask  [NB * TOPK * 32];
__device__ unsigned           d_rowany[NB * 32];

struct Ptrs {
    const float* cls[5];
    const float* ctr[5];
    const float* reg[5];
};

// exact replication of __fdiv_rn(inter,den) > 0.6f via exact double product
#define IOU_MID 0.6000000536441802978515625

// ---------------- XLA:CPU vectorized exp (Cephes clone, bit-exact vs reference) ----------------
__device__ __forceinline__ float xla_cpu_expf(float x) {
    x = fminf(x,  88.3762626647950f);
    x = fmaxf(x, -88.3762626647949f);
    float fx = floorf(fmaf(x, 1.44269504088896341f, 0.5f));
    float tmp = __fmul_rn(fx, 0.693359375f);
    float z   = __fmul_rn(fx, -2.12194440e-4f);
    x = __fsub_rn(x, tmp);
    x = __fsub_rn(x, z);
    z = __fmul_rn(x, x);
    float y = 1.9875691500e-4f;
    y = fmaf(y, x, 1.3981999507e-3f);
    y = fmaf(y, x, 8.3334519073e-3f);
    y = fmaf(y, x, 4.1665795894e-2f);
    y = fmaf(y, x, 1.6666665459e-1f);
    y = fmaf(y, x, 5.0000001201e-1f);
    y = fmaf(y, z, x);
    y = __fadd_rn(y, 1.0f);
    int n = (int)fx;
    float p2n = __int_as_float((n + 127) << 23);
    return __fmul_rn(y, p2n);
}
__device__ __forceinline__ float xla_sigmoid(float x) {
    float e = xla_cpu_expf(-x);
    return __fdiv_rn(1.0f, __fadd_rn(1.0f, e));
}

__device__ __forceinline__ void level_of(int a, int& lvl, int& off, int& hw, int& W, int& stride) {
    if      (a < 12800) { lvl = 0; off = 0;     hw = 12800; W = 128; stride = 8;   }
    else if (a < 16000) { lvl = 1; off = 12800; hw = 3200;  W = 64;  stride = 16;  }
    else if (a < 16800) { lvl = 2; off = 16000; hw = 800;   W = 32;  stride = 32;  }
    else if (a < 17008) { lvl = 3; off = 16800; hw = 208;   W = 16;  stride = 64;  }
    else                { lvl = 4; off = 17008; hw = 56;    W = 8;   stride = 128; }
}

// ---------------- kernel 1: pass-1 scores (max logit) + histogram ----------------
__global__ void score_kernel(Ptrs P) {
    __shared__ int shist[NBUCK];
    int b = blockIdx.y;
    for (int i = threadIdx.x; i < NBUCK; i += blockDim.x) shist[i] = 0;
    __syncthreads();

    int gt  = blockIdx.x * blockDim.x + threadIdx.x;
    int q   = gt >> 2;
    int sub = gt & 3;
    bool valid = (q < NQUAD);
    int qc = valid ? q : NQUAD - 1;   // clamp: in-bounds loads, full-warp shfl participation

    int a0 = qc * 4;
    int lvl, off, hw, W, stride;
    level_of(a0, lvl, off, hw, W, stride);
    int pix0 = a0 - off;

    const float* cp = P.cls[lvl] + (size_t)b * NCLS * hw + pix0 + (size_t)(sub * 20) * hw;
    float4 m = make_float4(-3.0e38f, -3.0e38f, -3.0e38f, -3.0e38f);
    #pragma unroll
    for (int c = 0; c < 20; c++) {
        float4 v = *(const float4*)(cp + (size_t)c * hw);
        m.x = fmaxf(m.x, v.x);
        m.y = fmaxf(m.y, v.y);
        m.z = fmaxf(m.z, v.z);
        m.w = fmaxf(m.w, v.w);
    }
    #pragma unroll
    for (int o = 1; o <= 2; o <<= 1) {
        m.x = fmaxf(m.x, __shfl_xor_sync(0xffffffffu, m.x, o));
        m.y = fmaxf(m.y, __shfl_xor_sync(0xffffffffu, m.y, o));
        m.z = fmaxf(m.z, __shfl_xor_sync(0xffffffffu, m.z, o));
        m.w = fmaxf(m.w, __shfl_xor_sync(0xffffffffu, m.w, o));
    }
    if (valid) {
        float mm = (sub == 0) ? m.x : (sub == 1) ? m.y : (sub == 2) ? m.z : m.w;
        float ct = P.ctr[lvl][(size_t)b * hw + pix0 + sub];
        float sc = __fmul_rn(xla_sigmoid(mm), xla_sigmoid(ct));
        d_score[b * NANCH + a0 + sub] = sc;

        int bu = (int)(sc * 2048.0f);
        bu = bu < 0 ? 0 : (bu > 2047 ? 2047 : bu);
        atomicAdd(&shist[bu], 1);
    }
    __syncthreads();
    for (int i = threadIdx.x; i < NBUCK; i += blockDim.x) {
        int v = shist[i];
        if (v) atomicAdd(&d_hist[b * NBUCK + i], v);
    }
}

// ---------------- kernel 2: cutoff (per batch), self-restores d_hist ----------------
__global__ void cutoff_kernel() {
    __shared__ int sbins[NBUCK];
    __shared__ int csum[64];
    int b = blockIdx.x;
    int tid = threadIdx.x;   // 256

    for (int i = tid; i < NBUCK; i += 256) {
        sbins[i] = d_hist[b * NBUCK + i];
        d_hist[b * NBUCK + i] = 0;          // same-thread restore: safe
    }
    __syncthreads();

    if (tid < 64) {
        int s = 0;
        for (int k = 0; k < 32; k++) s += sbins[2047 - (tid * 32 + k)];
        csum[tid] = s;
    }
    __syncthreads();
    if (tid == 0) {
        int cum = 0, cut = 0;
        for (int ch = 0; ch < 64; ch++) {
            if (cum + csum[ch] >= TOPK) {
                for (int k = 0; k < 32; k++) {
                    int bin = 2047 - (ch * 32 + k);
                    cum += sbins[bin];
                    if (cum >= TOPK) { cut = bin; break; }
                }
                break;
            }
            cum += csum[ch];
        }
        d_cut[b] = cut > 0 ? cut - 1 : 0;   // margin bucket for 2-ulp pass-1 slack
    }
}

// ---------------- kernel 3: wide compaction ----------------
__global__ void compact_kernel() {
    int b = blockIdx.y;
    int q = blockIdx.x * blockDim.x + threadIdx.x;
    if (q >= NQUAD) return;
    int cut = d_cut[b];
    float4 s4 = *(const float4*)(d_score + b * NANCH + q * 4);
    #pragma unroll
    for (int k = 0; k < 4; k++) {
        float sc = (k == 0) ? s4.x : (k == 1) ? s4.y : (k == 2) ? s4.z : s4.w;
        int bu = (int)(sc * 2048.0f);
        bu = bu < 0 ? 0 : (bu > 2047 ? 2047 : bu);
        if (bu >= cut) {
            int pos = atomicAdd(&d_cnt[b], 1);
            if (pos < CANDCAP) d_candanch[b * CANDCAP + pos] = q * 4 + k;
        }
    }
}

// ---------------- kernel 4: refine — HALF-WARP per candidate (5 loads/lane in flight) ----------------
// 16 lanes per candidate; lane covers classes l16+16k (k=0..4, exactly 80, ascending order).
// Width-16 shuffles with per-half masks: tail divergence between halves is safe.
__global__ void refine_kernel(Ptrs P) {
    int lane = threadIdx.x & 31;
    int half = lane >> 4;          // 0 or 1
    int l16  = lane & 15;
    unsigned hm = half ? 0xffff0000u : 0x0000ffffu;

    int b = blockIdx.y;
    int task = ((blockIdx.x * blockDim.x + threadIdx.x) >> 5) * 2 + half;   // half-warp task id
    const int TSTRIDE = ((64 * 256) >> 5) * 2;                              // 1024 tasks per batch

    int cnt = d_cnt[b];
    if (cnt > CANDCAP) cnt = CANDCAP;

    for (int slot = task; slot < cnt; slot += TSTRIDE) {
        int a = d_candanch[b * CANDCAP + slot];
        int lvl, off, hw, W, stride;
        level_of(a, lvl, off, hw, W, stride);
        int pix = a - off;

        const float* cp = P.cls[lvl] + (size_t)b * NCLS * hw + pix;
        float l0 = cp[(size_t)l16 * hw];
        float l1 = cp[(size_t)(l16 + 16) * hw];
        float l2 = cp[(size_t)(l16 + 32) * hw];
        float l3 = cp[(size_t)(l16 + 48) * hw];
        float l4 = cp[(size_t)(l16 + 64) * hw];

        float m = fmaxf(fmaxf(fmaxf(l0, l1), fmaxf(l2, l3)), l4);
        #pragma unroll
        for (int o = 8; o; o >>= 1) m = fmaxf(m, __shfl_xor_sync(hm, m, o, 16));
        float thr = __fsub_rn(m, 1.0e-3f);

        // per-lane best over window classes, ascending class order (strict > keeps first)
        float sb = -1.0f;
        int   cb = 0x7fffffff;
        if (l0 >= thr) { float s = xla_sigmoid(l0); if (s > sb) { sb = s; cb = l16; } }
        if (l1 >= thr) { float s = xla_sigmoid(l1); if (s > sb) { sb = s; cb = l16 + 16; } }
        if (l2 >= thr) { float s = xla_sigmoid(l2); if (s > sb) { sb = s; cb = l16 + 32; } }
        if (l3 >= thr) { float s = xla_sigmoid(l3); if (s > sb) { sb = s; cb = l16 + 48; } }
        if (l4 >= thr) { float s = xla_sigmoid(l4); if (s > sb) { sb = s; cb = l16 + 64; } }

        // half-warp reduce: larger s wins; equal s -> smaller c (first occurrence)
        #pragma unroll
        for (int o = 8; o; o >>= 1) {
            float so = __shfl_xor_sync(hm, sb, o, 16);
            int   co = __shfl_xor_sync(hm, cb, o, 16);
            if (so > sb || (so == sb && co < cb)) { sb = so; cb = co; }
        }

        if (l16 == 0) {
            int y = pix / W;
            int x = pix - y * W;
            float cx = (float)(x * stride + stride / 2);
            float cy = (float)(y * stride + stride / 2);

            float ctr = xla_sigmoid(P.ctr[lvl][(size_t)b * hw + pix]);
            float sc  = __fmul_rn(sb, ctr);

            const float* rp = P.reg[lvl] + (size_t)b * 4 * hw + pix;
            float r0 = rp[0];
            float r1 = rp[(size_t)hw];
            float r2 = rp[(size_t)2 * hw];
            float r3 = rp[(size_t)3 * hw];
            float4 bx;
            bx.x = __fsub_rn(cx, r0);
            bx.y = __fsub_rn(cy, r1);
            bx.z = __fadd_rn(cx, r2);
            bx.w = __fadd_rn(cy, r3);

            d_cls[b * NANCH + a] = cb + 1;
            d_box[b * NANCH + a] = bx;
            d_cand[b * CANDCAP + slot] =
                ((unsigned long long)__float_as_uint(sc) << 32) | (unsigned)(~(unsigned)a);
        }
    }
}

// ---------------- bitonic helpers ----------------
__device__ __forceinline__ unsigned long long bitonic_step(unsigned long long v, int i, int k, int j) {
    unsigned long long p = __shfl_xor_sync(0xffffffffu, v, j);
    bool desc  = ((i & k) == 0);
    bool lower = ((i & j) == 0);
    unsigned long long mx = v > p ? v : p;
    unsigned long long mn = v > p ? p : v;
    return (desc == lower) ? mx : mn;
}

// ---------------- kernel 5: sort + gather + M1 + offset boxes/areas, restores d_cnt ----------------
__global__ __launch_bounds__(1024, 1) void sort_kernel() {
    __shared__ unsigned long long keys[CANDCAP];
    __shared__ float smax[33];
    int b = blockIdx.x;
    int tid = threadIdx.x;  // 1024
    int lane = tid & 31;
    int w = tid >> 5;
    int cnt = d_cnt[b];
    if (cnt > CANDCAP) cnt = CANDCAP;
    int n = (cnt <= 2048) ? 2048 : CANDCAP;

    for (int i = tid; i < n; i += 1024) {
        unsigned long long v = (i < cnt) ? d_cand[b * CANDCAP + i] : 0ULL;
        #pragma unroll
        for (int k = 2; k <= 32; k <<= 1)
            #pragma unroll
            for (int j = k >> 1; j > 0; j >>= 1)
                v = bitonic_step(v, i, k, j);
        keys[i] = v;
    }
    __syncthreads();
    if (tid == 0) d_cnt[b] = 0;          // restore for next replay (after barrier: race-free)

    for (int k = 64; k <= n; k <<= 1) {
        for (int j = k >> 1; j >= 32; j >>= 1) {
            for (int i = tid; i < n; i += 1024) {
                int ixj = i ^ j;
                if (ixj > i) {
                    unsigned long long A = keys[i], Bk = keys[ixj];
                    bool desc = ((i & k) == 0);
                    bool sw = desc ? (A < Bk) : (A > Bk);
                    if (sw) { keys[i] = Bk; keys[ixj] = A; }
                }
            }
            __syncthreads();
        }
        for (int i = tid; i < n; i += 1024) {
            unsigned long long v = keys[i];
            #pragma unroll
            for (int j = 16; j > 0; j >>= 1)
                v = bitonic_step(v, i, k, j);
            keys[i] = v;
        }
        __syncthreads();
    }

    float sc = 0.0f; int cls = 0; float4 bx = make_float4(0.f, 0.f, 0.f, 0.f);
    float mloc = -3.0e38f;
    if (tid < TOPK) {
        unsigned long long key = keys[tid];
        sc = __uint_as_float((unsigned)(key >> 32));
        int a = (int)(~(unsigned)(key & 0xFFFFFFFFu));
        int src = b * NANCH + a;
        cls = d_cls[src];
        bx  = d_box[src];
        int dst = b * TOPK + tid;
        d_tscore[dst] = sc;
        d_tcls[dst]   = cls;
        d_tbox[dst]   = bx;
        mloc = fmaxf(fmaxf(bx.x, bx.y), fmaxf(bx.z, bx.w));
    }
    for (int o = 16; o; o >>= 1) mloc = fmaxf(mloc, __shfl_xor_sync(0xffffffffu, mloc, o));
    if (lane == 0) smax[w] = mloc;
    __syncthreads();
    if (w == 0) {
        float mm = smax[lane];
        for (int o = 16; o; o >>= 1) mm = fmaxf(mm, __shfl_xor_sync(0xffffffffu, mm, o));
        if (lane == 0) smax[32] = mm;
    }
    __syncthreads();
    float M1 = __fadd_rn(smax[32], 1.0f);

    if (tid < TOPK) {
        float offv = __fmul_rn((float)cls, M1);
        float4 nb;
        nb.x = __fadd_rn(bx.x, offv);
        nb.y = __fadd_rn(bx.y, offv);
        nb.z = __fadd_rn(bx.z, offv);
        nb.w = __fadd_rn(bx.w, offv);
        int dst = b * TOPK + tid;
        d_nbox[dst]  = nb;
        d_narea[dst] = __fmul_rn(__fadd_rn(__fsub_rn(nb.z, nb.x), 1.0f),
                                 __fadd_rn(__fsub_rn(nb.w, nb.y), 1.0f));
    }
}

// ---------------- kernel 6: NMS bitmask, zero-words skipped (16 blocks/batch) ----------------
__global__ void mask_kernel() {
    __shared__ float4 sbox[TOPK];
    __shared__ float  sarea[TOPK];
    int b = blockIdx.y;
    int tid = threadIdx.x;   // 1024
    int lane = tid & 31;
    int w = tid >> 5;
    for (int i = tid; i < TOPK; i += 1024) {
        sbox[i]  = d_nbox[b * TOPK + i];
        sarea[i] = d_narea[b * TOPK + i];
    }
    __syncthreads();

    int gw = blockIdx.x * 32 + w;   // 0..511
    for (int i = gw; i < TOPK; i += 512) {
        float4 bi = sbox[i];
        float ai = sarea[i];
        unsigned any = 0;
        for (int wd = i >> 5; wd < 32; wd++) {
            int j = wd * 32 + lane;
            bool pred = false;
            if (j < TOPK && j > i) {
                float4 bj = sbox[j];
                float xmin = fmaxf(bi.x, bj.x);
                float ymin = fmaxf(bi.y, bj.y);
                float xmax = fminf(bi.z, bj.z);
                float ymax = fminf(bi.w, bj.w);
                float iw = fmaxf(__fsub_rn(xmax, xmin), 0.0f);
                float ih = fmaxf(__fsub_rn(ymax, ymin), 0.0f);
                float inter = __fmul_rn(iw, ih);
                float den = __fsub_rn(__fadd_rn(ai, sarea[j]), inter);
                pred = (double)inter > IOU_MID * (double)den;
            }
            unsigned bal = __ballot_sync(0xffffffffu, pred);
            if (lane == 0 && bal) d_mask[(b * TOPK + i) * 32 + wd] = bal;
            any |= bal;
        }
        if (lane == 0 && any) atomicOr(&d_rowany[b * 32 + (i >> 5)], 1u << (i & 31));
    }
}

// ---------------- kernel 7: greedy sweep (compacted flagged-row prefetch) + outputs ----------------
__global__ void sweep_kernel(float* __restrict__ out) {
    extern __shared__ char smem_raw[];
    unsigned* cmask  = (unsigned*)(smem_raw);                 // flagged rows only
    float*    sscore = (float*)(smem_raw + 128000);
    int*      scls   = (int*)(smem_raw + 132000);
    unsigned* rowAny = (unsigned*)(smem_raw + 136000);
    unsigned* remw   = (unsigned*)(smem_raw + 136128);
    int*      rbase  = (int*)(smem_raw + 136256);

    int b = blockIdx.x;
    int tid = threadIdx.x;           // 1024
    int lane = tid & 31;
    int w = tid >> 5;

    for (int i = tid; i < TOPK; i += 1024) {
        sscore[i] = d_tscore[b * TOPK + i];
        scls[i]   = d_tcls[b * TOPK + i];
    }
    if (tid < 32) rowAny[tid] = d_rowany[b * 32 + tid];
    __syncthreads();

    if (tid == 0) {
        int s = 0;
        for (int c = 0; c < 32; c++) { rbase[c] = s; s += __popc(rowAny[c]); }
    }
    __syncthreads();

    {
        unsigned bits = rowAny[w];
        int k = rbase[w];
        while (bits) {
            int bpos = __ffs(bits) - 1;
            bits &= bits - 1;
            int i = w * 32 + bpos;
            cmask[k * 32 + lane] = d_mask[(b * TOPK + i) * 32 + lane];
            k++;
        }
    }

    {
        bool invalid = (tid >= TOPK) || (sscore[tid] < 0.05f);
        unsigned bal = __ballot_sync(0xffffffffu, invalid);
        if (lane == 0) remw[w] = bal;
    }
    __syncthreads();

    if (w == 0) {
        unsigned rem = remw[lane];
        int k = 0;
        for (int c = 0; c < 32; c++) {
            unsigned bits = rowAny[c];
            while (bits) {
                int bpos = __ffs(bits) - 1;
                bits &= bits - 1;
                unsigned wi = __shfl_sync(0xffffffffu, rem, c);
                if (!((wi >> bpos) & 1u)) rem |= cmask[k * 32 + lane];
                k++;
            }
        }
        remw[lane] = rem;
    }
    __syncthreads();

    float* out_sc = out;
    float* out_cl = out + NB * TOPK;
    float* out_bx = out + 2 * NB * TOPK;
    for (int i = tid; i < TOPK; i += 1024) {
        bool kp = !((remw[i >> 5] >> (i & 31)) & 1u);
        out_sc[b * TOPK + i] = kp ? sscore[i] : 0.0f;
        out_cl[b * TOPK + i] = kp ? (float)scls[i] : 0.0f;
        float4 ob = d_tbox[b * TOPK + i];
        float4 r;
        r.x = kp ? ob.x : 0.0f;
        r.y = kp ? ob.y : 0.0f;
        r.z = kp ? ob.z : 0.0f;
        r.w = kp ? ob.w : 0.0f;
        ((float4*)out_bx)[b * TOPK + i] = r;
    }
}

// ---------------- host ----------------
extern "C" void kernel_launch(void* const* d_in, const int* in_sizes, int n_in,
                              void* d_out, int out_size) {
    Ptrs P;
    if (n_in >= 15 && in_sizes[1] == 4096000) {
        for (int i = 0; i < 5; i++) {
            P.cls[i] = (const float*)d_in[i];
            P.ctr[i] = (const float*)d_in[5 + i];
            P.reg[i] = (const float*)d_in[10 + i];
        }
    } else {
        for (int i = 0; i < 5; i++) {
            P.cls[i] = (const float*)d_in[3 * i];
            P.ctr[i] = (const float*)d_in[3 * i + 1];
            P.reg[i] = (const float*)d_in[3 * i + 2];
        }
    }

    static bool attr_set = false;
    if (!attr_set) {
        cudaFuncSetAttribute(sweep_kernel, cudaFuncAttributeMaxDynamicSharedMemorySize, 136448);
        attr_set = true;
    }

    // launch order: score(1) cutoff(2) compact(3) refine(4=ncu capture) sort(5) mask(6) sweep(7)
    score_kernel<<<dim3((NANCH + 255) / 256, NB), 256>>>(P);
    cutoff_kernel<<<NB, 256>>>();
    compact_kernel<<<dim3((NQUAD + 255) / 256, NB), 256>>>();
    refine_kernel<<<dim3(64, NB), 256>>>(P);
    sort_kernel<<<NB, 1024>>>();
    mask_kernel<<<dim3(16, NB), 1024>>>();
    sweep_kernel<<<NB, 1024, 136448>>>((float*)d_out);
}

// round 17
// speedup vs baseline: 1.0923x; 1.0923x over previous
#include <cuda_runtime.h>
#include <stdint.h>

#define NB      16
#define NCLS    80
#define NANCH   17064
#define NQUAD   (NANCH / 4)     // 4266
#define TOPK    1000
#define NBUCK   2048
#define CANDCAP 4096

// ---------------- scratch (static device globals, zero-initialized at load) ----------------
__device__ float              d_score[NB * NANCH];
__device__ int                d_cls  [NB * NANCH];
__device__ float4             d_box  [NB * NANCH];
__device__ int                d_hist [NB * NBUCK];
__device__ int                d_cut  [NB];
__device__ int                d_cnt  [NB];
__device__ int                d_candanch[NB * CANDCAP];
__device__ unsigned long long d_cand [NB * CANDCAP];
__device__ float              d_tscore[NB * TOPK];
__device__ int                d_tcls  [NB * TOPK];
__device__ float4             d_tbox  [NB * TOPK];
__device__ float4             d_nbox  [NB * TOPK];
__device__ float              d_narea [NB * TOPK];
__device__ unsigned           d_mask  [NB * TOPK * 32];
__device__ unsigned           d_rowany[NB * 32];

struct Ptrs {
    const float* cls[5];
    const float* ctr[5];
    const float* reg[5];
};

// exact replication of __fdiv_rn(inter,den) > 0.6f via exact double product
#define IOU_MID 0.6000000536441802978515625

// ---------------- XLA:CPU vectorized exp (Cephes clone, bit-exact vs reference) ----------------
__device__ __forceinline__ float xla_cpu_expf(float x) {
    x = fminf(x,  88.3762626647950f);
    x = fmaxf(x, -88.3762626647949f);
    float fx = floorf(fmaf(x, 1.44269504088896341f, 0.5f));
    float tmp = __fmul_rn(fx, 0.693359375f);
    float z   = __fmul_rn(fx, -2.12194440e-4f);
    x = __fsub_rn(x, tmp);
    x = __fsub_rn(x, z);
    z = __fmul_rn(x, x);
    float y = 1.9875691500e-4f;
    y = fmaf(y, x, 1.3981999507e-3f);
    y = fmaf(y, x, 8.3334519073e-3f);
    y = fmaf(y, x, 4.1665795894e-2f);
    y = fmaf(y, x, 1.6666665459e-1f);
    y = fmaf(y, x, 5.0000001201e-1f);
    y = fmaf(y, z, x);
    y = __fadd_rn(y, 1.0f);
    int n = (int)fx;
    float p2n = __int_as_float((n + 127) << 23);
    return __fmul_rn(y, p2n);
}
__device__ __forceinline__ float xla_sigmoid(float x) {
    float e = xla_cpu_expf(-x);
    return __fdiv_rn(1.0f, __fadd_rn(1.0f, e));
}

__device__ __forceinline__ void level_of(int a, int& lvl, int& off, int& hw, int& W, int& stride) {
    if      (a < 12800) { lvl = 0; off = 0;     hw = 12800; W = 128; stride = 8;   }
    else if (a < 16000) { lvl = 1; off = 12800; hw = 3200;  W = 64;  stride = 16;  }
    else if (a < 16800) { lvl = 2; off = 16000; hw = 800;   W = 32;  stride = 32;  }
    else if (a < 17008) { lvl = 3; off = 16800; hw = 208;   W = 16;  stride = 64;  }
    else                { lvl = 4; off = 17008; hw = 56;    W = 8;   stride = 128; }
}

// ---------------- kernel 1: pass-1 scores (max logit) + histogram ----------------
__global__ void score_kernel(Ptrs P) {
    __shared__ int shist[NBUCK];
    int b = blockIdx.y;
    for (int i = threadIdx.x; i < NBUCK; i += blockDim.x) shist[i] = 0;
    __syncthreads();

    int gt  = blockIdx.x * blockDim.x + threadIdx.x;
    int q   = gt >> 2;
    int sub = gt & 3;
    bool valid = (q < NQUAD);
    int qc = valid ? q : NQUAD - 1;   // clamp: in-bounds loads, full-warp shfl participation

    int a0 = qc * 4;
    int lvl, off, hw, W, stride;
    level_of(a0, lvl, off, hw, W, stride);
    int pix0 = a0 - off;

    const float* cp = P.cls[lvl] + (size_t)b * NCLS * hw + pix0 + (size_t)(sub * 20) * hw;
    float4 m = make_float4(-3.0e38f, -3.0e38f, -3.0e38f, -3.0e38f);
    #pragma unroll
    for (int c = 0; c < 20; c++) {
        float4 v = *(const float4*)(cp + (size_t)c * hw);
        m.x = fmaxf(m.x, v.x);
        m.y = fmaxf(m.y, v.y);
        m.z = fmaxf(m.z, v.z);
        m.w = fmaxf(m.w, v.w);
    }
    #pragma unroll
    for (int o = 1; o <= 2; o <<= 1) {
        m.x = fmaxf(m.x, __shfl_xor_sync(0xffffffffu, m.x, o));
        m.y = fmaxf(m.y, __shfl_xor_sync(0xffffffffu, m.y, o));
        m.z = fmaxf(m.z, __shfl_xor_sync(0xffffffffu, m.z, o));
        m.w = fmaxf(m.w, __shfl_xor_sync(0xffffffffu, m.w, o));
    }
    if (valid) {
        float mm = (sub == 0) ? m.x : (sub == 1) ? m.y : (sub == 2) ? m.z : m.w;
        float ct = P.ctr[lvl][(size_t)b * hw + pix0 + sub];
        float sc = __fmul_rn(xla_sigmoid(mm), xla_sigmoid(ct));
        d_score[b * NANCH + a0 + sub] = sc;

        int bu = (int)(sc * 2048.0f);
        bu = bu < 0 ? 0 : (bu > 2047 ? 2047 : bu);
        atomicAdd(&shist[bu], 1);
    }
    __syncthreads();
    for (int i = threadIdx.x; i < NBUCK; i += blockDim.x) {
        int v = shist[i];
        if (v) atomicAdd(&d_hist[b * NBUCK + i], v);
    }
}

// ---------------- kernel 2: cutoff (per batch), self-restores d_hist ----------------
__global__ void cutoff_kernel() {
    __shared__ int sbins[NBUCK];
    __shared__ int csum[64];
    int b = blockIdx.x;
    int tid = threadIdx.x;   // 256

    for (int i = tid; i < NBUCK; i += 256) {
        sbins[i] = d_hist[b * NBUCK + i];
        d_hist[b * NBUCK + i] = 0;          // same-thread restore: safe
    }
    __syncthreads();

    if (tid < 64) {
        int s = 0;
        for (int k = 0; k < 32; k++) s += sbins[2047 - (tid * 32 + k)];
        csum[tid] = s;
    }
    __syncthreads();
    if (tid == 0) {
        int cum = 0, cut = 0;
        for (int ch = 0; ch < 64; ch++) {
            if (cum + csum[ch] >= TOPK) {
                for (int k = 0; k < 32; k++) {
                    int bin = 2047 - (ch * 32 + k);
                    cum += sbins[bin];
                    if (cum >= TOPK) { cut = bin; break; }
                }
                break;
            }
            cum += csum[ch];
        }
        d_cut[b] = cut > 0 ? cut - 1 : 0;   // margin bucket for 2-ulp pass-1 slack
    }
}

// ---------------- kernel 3: wide compaction ----------------
__global__ void compact_kernel() {
    int b = blockIdx.y;
    int q = blockIdx.x * blockDim.x + threadIdx.x;
    if (q >= NQUAD) return;
    int cut = d_cut[b];
    float4 s4 = *(const float4*)(d_score + b * NANCH + q * 4);
    #pragma unroll
    for (int k = 0; k < 4; k++) {
        float sc = (k == 0) ? s4.x : (k == 1) ? s4.y : (k == 2) ? s4.z : s4.w;
        int bu = (int)(sc * 2048.0f);
        bu = bu < 0 ? 0 : (bu > 2047 ? 2047 : bu);
        if (bu >= cut) {
            int pos = atomicAdd(&d_cnt[b], 1);
            if (pos < CANDCAP) d_candanch[b * CANDCAP + pos] = q * 4 + k;
        }
    }
}

// ---------------- kernel 4: refine — HALF-WARP per candidate (5 loads/lane in flight) ----------------
__global__ void refine_kernel(Ptrs P) {
    int lane = threadIdx.x & 31;
    int half = lane >> 4;          // 0 or 1
    int l16  = lane & 15;
    unsigned hm = half ? 0xffff0000u : 0x0000ffffu;

    int b = blockIdx.y;
    int task = ((blockIdx.x * blockDim.x + threadIdx.x) >> 5) * 2 + half;   // half-warp task id
    const int TSTRIDE = ((64 * 256) >> 5) * 2;                              // 1024 tasks per batch

    int cnt = d_cnt[b];
    if (cnt > CANDCAP) cnt = CANDCAP;

    for (int slot = task; slot < cnt; slot += TSTRIDE) {
        int a = d_candanch[b * CANDCAP + slot];
        int lvl, off, hw, W, stride;
        level_of(a, lvl, off, hw, W, stride);
        int pix = a - off;

        const float* cp = P.cls[lvl] + (size_t)b * NCLS * hw + pix;
        float l0 = cp[(size_t)l16 * hw];
        float l1 = cp[(size_t)(l16 + 16) * hw];
        float l2 = cp[(size_t)(l16 + 32) * hw];
        float l3 = cp[(size_t)(l16 + 48) * hw];
        float l4 = cp[(size_t)(l16 + 64) * hw];

        float m = fmaxf(fmaxf(fmaxf(l0, l1), fmaxf(l2, l3)), l4);
        #pragma unroll
        for (int o = 8; o; o >>= 1) m = fmaxf(m, __shfl_xor_sync(hm, m, o, 16));
        float thr = __fsub_rn(m, 1.0e-3f);

        float sb = -1.0f;
        int   cb = 0x7fffffff;
        if (l0 >= thr) { float s = xla_sigmoid(l0); if (s > sb) { sb = s; cb = l16; } }
        if (l1 >= thr) { float s = xla_sigmoid(l1); if (s > sb) { sb = s; cb = l16 + 16; } }
        if (l2 >= thr) { float s = xla_sigmoid(l2); if (s > sb) { sb = s; cb = l16 + 32; } }
        if (l3 >= thr) { float s = xla_sigmoid(l3); if (s > sb) { sb = s; cb = l16 + 48; } }
        if (l4 >= thr) { float s = xla_sigmoid(l4); if (s > sb) { sb = s; cb = l16 + 64; } }

        #pragma unroll
        for (int o = 8; o; o >>= 1) {
            float so = __shfl_xor_sync(hm, sb, o, 16);
            int   co = __shfl_xor_sync(hm, cb, o, 16);
            if (so > sb || (so == sb && co < cb)) { sb = so; cb = co; }
        }

        if (l16 == 0) {
            int y = pix / W;
            int x = pix - y * W;
            float cx = (float)(x * stride + stride / 2);
            float cy = (float)(y * stride + stride / 2);

            float ctr = xla_sigmoid(P.ctr[lvl][(size_t)b * hw + pix]);
            float sc  = __fmul_rn(sb, ctr);

            const float* rp = P.reg[lvl] + (size_t)b * 4 * hw + pix;
            float r0 = rp[0];
            float r1 = rp[(size_t)hw];
            float r2 = rp[(size_t)2 * hw];
            float r3 = rp[(size_t)3 * hw];
            float4 bx;
            bx.x = __fsub_rn(cx, r0);
            bx.y = __fsub_rn(cy, r1);
            bx.z = __fadd_rn(cx, r2);
            bx.w = __fadd_rn(cy, r3);

            d_cls[b * NANCH + a] = cb + 1;
            d_box[b * NANCH + a] = bx;
            d_cand[b * CANDCAP + slot] =
                ((unsigned long long)__float_as_uint(sc) << 32) | (unsigned)(~(unsigned)a);
        }
    }
}

// ---------------- bitonic helpers ----------------
__device__ __forceinline__ unsigned long long bitonic_step(unsigned long long v, int i, int k, int j) {
    unsigned long long p = __shfl_xor_sync(0xffffffffu, v, j);
    bool desc  = ((i & k) == 0);
    bool lower = ((i & j) == 0);
    unsigned long long mx = v > p ? v : p;
    unsigned long long mn = v > p ? p : v;
    return (desc == lower) ? mx : mn;
}

// ---------------- kernel 5: sort + gather + M1 + offset boxes/areas, restores d_cnt ----------------
__global__ __launch_bounds__(1024, 1) void sort_kernel() {
    __shared__ unsigned long long keys[CANDCAP];
    __shared__ float smax[33];
    int b = blockIdx.x;
    int tid = threadIdx.x;  // 1024
    int lane = tid & 31;
    int w = tid >> 5;
    int cnt = d_cnt[b];
    if (cnt > CANDCAP) cnt = CANDCAP;
    int n = (cnt <= 2048) ? 2048 : CANDCAP;

    for (int i = tid; i < n; i += 1024) {
        unsigned long long v = (i < cnt) ? d_cand[b * CANDCAP + i] : 0ULL;
        #pragma unroll
        for (int k = 2; k <= 32; k <<= 1)
            #pragma unroll
            for (int j = k >> 1; j > 0; j >>= 1)
                v = bitonic_step(v, i, k, j);
        keys[i] = v;
    }
    __syncthreads();
    if (tid == 0) d_cnt[b] = 0;          // restore for next replay (after barrier: race-free)

    for (int k = 64; k <= n; k <<= 1) {
        for (int j = k >> 1; j >= 32; j >>= 1) {
            for (int i = tid; i < n; i += 1024) {
                int ixj = i ^ j;
                if (ixj > i) {
                    unsigned long long A = keys[i], Bk = keys[ixj];
                    bool desc = ((i & k) == 0);
                    bool sw = desc ? (A < Bk) : (A > Bk);
                    if (sw) { keys[i] = Bk; keys[ixj] = A; }
                }
            }
            __syncthreads();
        }
        for (int i = tid; i < n; i += 1024) {
            unsigned long long v = keys[i];
            #pragma unroll
            for (int j = 16; j > 0; j >>= 1)
                v = bitonic_step(v, i, k, j);
            keys[i] = v;
        }
        __syncthreads();
    }

    float sc = 0.0f; int cls = 0; float4 bx = make_float4(0.f, 0.f, 0.f, 0.f);
    float mloc = -3.0e38f;
    if (tid < TOPK) {
        unsigned long long key = keys[tid];
        sc = __uint_as_float((unsigned)(key >> 32));
        int a = (int)(~(unsigned)(key & 0xFFFFFFFFu));
        int src = b * NANCH + a;
        cls = d_cls[src];
        bx  = d_box[src];
        int dst = b * TOPK + tid;
        d_tscore[dst] = sc;
        d_tcls[dst]   = cls;
        d_tbox[dst]   = bx;
        mloc = fmaxf(fmaxf(bx.x, bx.y), fmaxf(bx.z, bx.w));
    }
    for (int o = 16; o; o >>= 1) mloc = fmaxf(mloc, __shfl_xor_sync(0xffffffffu, mloc, o));
    if (lane == 0) smax[w] = mloc;
    __syncthreads();
    if (w == 0) {
        float mm = smax[lane];
        for (int o = 16; o; o >>= 1) mm = fmaxf(mm, __shfl_xor_sync(0xffffffffu, mm, o));
        if (lane == 0) smax[32] = mm;
    }
    __syncthreads();
    float M1 = __fadd_rn(smax[32], 1.0f);

    if (tid < TOPK) {
        float offv = __fmul_rn((float)cls, M1);
        float4 nb;
        nb.x = __fadd_rn(bx.x, offv);
        nb.y = __fadd_rn(bx.y, offv);
        nb.z = __fadd_rn(bx.z, offv);
        nb.w = __fadd_rn(bx.w, offv);
        int dst = b * TOPK + tid;
        d_nbox[dst]  = nb;
        d_narea[dst] = __fmul_rn(__fadd_rn(__fsub_rn(nb.z, nb.x), 1.0f),
                                 __fadd_rn(__fsub_rn(nb.w, nb.y), 1.0f));
    }
}

// ---------------- kernel 6: NMS bitmask, zero-words skipped (8 blocks/batch) ----------------
__global__ void mask_kernel() {
    __shared__ float4 sbox[TOPK];
    __shared__ float  sarea[TOPK];
    int b = blockIdx.y;
    int tid = threadIdx.x;   // 1024
    int lane = tid & 31;
    int w = tid >> 5;
    for (int i = tid; i < TOPK; i += 1024) {
        sbox[i]  = d_nbox[b * TOPK + i];
        sarea[i] = d_narea[b * TOPK + i];
    }
    __syncthreads();

    int gw = blockIdx.x * 32 + w;   // 0..255
    for (int i = gw; i < TOPK; i += 256) {
        float4 bi = sbox[i];
        float ai = sarea[i];
        unsigned any = 0;
        for (int wd = i >> 5; wd < 32; wd++) {
            int j = wd * 32 + lane;
            bool pred = false;
            if (j < TOPK && j > i) {
                float4 bj = sbox[j];
                float xmin = fmaxf(bi.x, bj.x);
                float ymin = fmaxf(bi.y, bj.y);
                float xmax = fminf(bi.z, bj.z);
                float ymax = fminf(bi.w, bj.w);
                float iw = fmaxf(__fsub_rn(xmax, xmin), 0.0f);
                float ih = fmaxf(__fsub_rn(ymax, ymin), 0.0f);
                float inter = __fmul_rn(iw, ih);
                float den = __fsub_rn(__fadd_rn(ai, sarea[j]), inter);
                pred = (double)inter > IOU_MID * (double)den;
            }
            unsigned bal = __ballot_sync(0xffffffffu, pred);
            if (lane == 0 && bal) d_mask[(b * TOPK + i) * 32 + wd] = bal;
            any |= bal;
        }
        if (lane == 0 && any) atomicOr(&d_rowany[b * 32 + (i >> 5)], 1u << (i & 31));
    }
}

// ---------------- kernel 7: greedy sweep (compacted flagged-row prefetch) + outputs ----------------
__global__ void sweep_kernel(float* __restrict__ out) {
    extern __shared__ char smem_raw[];
    unsigned* cmask  = (unsigned*)(smem_raw);                 // flagged rows only
    float*    sscore = (float*)(smem_raw + 128000);
    int*      scls   = (int*)(smem_raw + 132000);
    unsigned* rowAny = (unsigned*)(smem_raw + 136000);
    unsigned* remw   = (unsigned*)(smem_raw + 136128);
    int*      rbase  = (int*)(smem_raw + 136256);

    int b = blockIdx.x;
    int tid = threadIdx.x;           // 1024
    int lane = tid & 31;
    int w = tid >> 5;

    for (int i = tid; i < TOPK; i += 1024) {
        sscore[i] = d_tscore[b * TOPK + i];
        scls[i]   = d_tcls[b * TOPK + i];
    }
    if (tid < 32) rowAny[tid] = d_rowany[b * 32 + tid];
    __syncthreads();

    if (tid == 0) {
        int s = 0;
        for (int c = 0; c < 32; c++) { rbase[c] = s; s += __popc(rowAny[c]); }
    }
    __syncthreads();

    {
        unsigned bits = rowAny[w];
        int k = rbase[w];
        while (bits) {
            int bpos = __ffs(bits) - 1;
            bits &= bits - 1;
            int i = w * 32 + bpos;
            cmask[k * 32 + lane] = d_mask[(b * TOPK + i) * 32 + lane];
            k++;
        }
    }

    {
        bool invalid = (tid >= TOPK) || (sscore[tid] < 0.05f);
        unsigned bal = __ballot_sync(0xffffffffu, invalid);
        if (lane == 0) remw[w] = bal;
    }
    __syncthreads();

    if (w == 0) {
        unsigned rem = remw[lane];
        int k = 0;
        for (int c = 0; c < 32; c++) {
            unsigned bits = rowAny[c];
            while (bits) {
                int bpos = __ffs(bits) - 1;
                bits &= bits - 1;
                unsigned wi = __shfl_sync(0xffffffffu, rem, c);
                if (!((wi >> bpos) & 1u)) rem |= cmask[k * 32 + lane];
                k++;
            }
        }
        remw[lane] = rem;
    }
    __syncthreads();

    float* out_sc = out;
    float* out_cl = out + NB * TOPK;
    float* out_bx = out + 2 * NB * TOPK;
    for (int i = tid; i < TOPK; i += 1024) {
        bool kp = !((remw[i >> 5] >> (i & 31)) & 1u);
        out_sc[b * TOPK + i] = kp ? sscore[i] : 0.0f;
        out_cl[b * TOPK + i] = kp ? (float)scls[i] : 0.0f;
        float4 ob = d_tbox[b * TOPK + i];
        float4 r;
        r.x = kp ? ob.x : 0.0f;
        r.y = kp ? ob.y : 0.0f;
        r.z = kp ? ob.z : 0.0f;
        r.w = kp ? ob.w : 0.0f;
        ((float4*)out_bx)[b * TOPK + i] = r;
    }
}

// ---------------- host ----------------
extern "C" void kernel_launch(void* const* d_in, const int* in_sizes, int n_in,
                              void* d_out, int out_size) {
    Ptrs P;
    if (n_in >= 15 && in_sizes[1] == 4096000) {
        for (int i = 0; i < 5; i++) {
            P.cls[i] = (const float*)d_in[i];
            P.ctr[i] = (const float*)d_in[5 + i];
            P.reg[i] = (const float*)d_in[10 + i];
        }
    } else {
        for (int i = 0; i < 5; i++) {
            P.cls[i] = (const float*)d_in[3 * i];
            P.ctr[i] = (const float*)d_in[3 * i + 1];
            P.reg[i] = (const float*)d_in[3 * i + 2];
        }
    }

    static bool attr_set = false;
    if (!attr_set) {
        cudaFuncSetAttribute(sweep_kernel, cudaFuncAttributeMaxDynamicSharedMemorySize, 136448);
        attr_set = true;
    }

    // launch order: score(1) cutoff(2) compact(3) refine(4=ncu capture) sort(5) mask(6) sweep(7)
    score_kernel<<<dim3((NANCH + 255) / 256, NB), 256>>>(P);
    cutoff_kernel<<<NB, 256>>>();
    compact_kernel<<<dim3((NQUAD + 255) / 256, NB), 256>>>();
    refine_kernel<<<dim3(64, NB), 256>>>(P);
    sort_kernel<<<NB, 1024>>>();
    mask_kernel<<<dim3(8, NB), 1024>>>();
    sweep_kernel<<<NB, 1024, 136448>>>((float*)d_out);
}